// round 12
// baseline (speedup 1.0000x reference)
#include <cuda_runtime.h>
#include <cstddef>
#include <cstdint>

#define S_DIM 128
#define L_DIM 512
#define IN_DIM 256
#define PROJ 32
#define OUT_F 128
#define JT 16

using ull = unsigned long long;

__device__ __forceinline__ ull pack2(float lo, float hi) {
    ull r; asm("mov.b64 %0, {%1,%2};" : "=l"(r) : "f"(lo), "f"(hi)); return r;
}
__device__ __forceinline__ void unpack2(ull v, float& lo, float& hi) {
    asm("mov.b64 {%0,%1}, %2;" : "=f"(lo), "=f"(hi) : "l"(v));
}
__device__ __forceinline__ void fma2(ull& d, ull a, ull b) {
    asm("fma.rn.f32x2 %0, %1, %2, %0;" : "+l"(d) : "l"(a), "l"(b));
}
__device__ __forceinline__ void cp16(unsigned dst, const void* src) {
    asm volatile("cp.async.cg.shared.global [%0], [%1], 16;" :: "r"(dst), "l"(src));
}
__device__ __forceinline__ void cpcommit() { asm volatile("cp.async.commit_group;" ::: "memory"); }
__device__ __forceinline__ void cpwait2()  { asm volatile("cp.async.wait_group 2;" ::: "memory"); }
__device__ __forceinline__ void cpwait1()  { asm volatile("cp.async.wait_group 1;" ::: "memory"); }
__device__ __forceinline__ void cpwait0()  { asm volatile("cp.async.wait_group 0;" ::: "memory"); }

// l[s,i,d] as Lbuf[(i*128+s)*32+d]; r[s,j,e] as Rbuf[(s*512+j)*32+e]
__device__ float g_Lbuf[L_DIM * S_DIM * PROJ];   // 8 MB
__device__ float g_Rbuf[S_DIM * L_DIM * PROJ];   // 8 MB

// ---------------------------------------------------------------------------
// Kernel A: LayerNorm + projection + mask. 32 rows/block (W amortized 4x).
// ---------------------------------------------------------------------------
#define KA_WPITCH 66
#define KA_SMEM_FLOATS (IN_DIM * KA_WPITCH + 32 * IN_DIM + 64)

__global__ void __launch_bounds__(256) Node2Edge_kA(
    const float* __restrict__ x, const float* __restrict__ mask,
    const float* __restrict__ W, const float* __restrict__ b)
{
    extern __shared__ float sma[];
    float* W_sm  = sma;                              // 256*66
    float* x_sm  = sma + IN_DIM * KA_WPITCH;         // 32*256
    float* sW_sm = x_sm + 32 * IN_DIM;               // 64
    const int t = threadIdx.x;

    {
        const float4* Wg = (const float4*)W;
        #pragma unroll
        for (int q = 0; q < 16; q++) {
            int i4 = t + 256 * q;
            float4 v = Wg[i4];
            int lin = i4 * 4;
            int k = lin >> 8, c = lin & 255;
            W_sm[(c + 0) * KA_WPITCH + k] = v.x;
            W_sm[(c + 1) * KA_WPITCH + k] = v.y;
            W_sm[(c + 2) * KA_WPITCH + k] = v.z;
            W_sm[(c + 3) * KA_WPITCH + k] = v.w;
        }
    }
    const int row0 = blockIdx.x * 32;
    {
        const float4* xs = (const float4*)(x + (size_t)row0 * IN_DIM);
        float4* xd = (float4*)x_sm;
        #pragma unroll
        for (int q = 0; q < 8; q++) xd[t + 256 * q] = xs[t + 256 * q];
    }
    __syncthreads();

    if (t < 64) {
        float s = 0.f;
        #pragma unroll 8
        for (int c = 0; c < IN_DIM; c++) s += W_sm[c * KA_WPITCH + t];
        sW_sm[t] = s;
    }
    __syncthreads();

    const int w = t >> 5, lane = t & 31;
    #pragma unroll 1
    for (int rr = 0; rr < 4; rr++) {
        const int row_local = w * 4 + rr;
        float s1 = 0.f, s2 = 0.f;
        #pragma unroll
        for (int q = 0; q < 8; q++) {
            float v = x_sm[row_local * IN_DIM + lane + 32 * q];
            s1 += v; s2 += v * v;
        }
        #pragma unroll
        for (int off = 16; off; off >>= 1) {
            s1 += __shfl_xor_sync(0xffffffffu, s1, off);
            s2 += __shfl_xor_sync(0xffffffffu, s2, off);
        }
        const float mu  = s1 * (1.f / 256.f);
        const float var = s2 * (1.f / 256.f) - mu * mu;
        const float rs  = rsqrtf(var + 1e-5f);

        float a0 = 0.f, a1 = 0.f;
        {
            const float* xr = x_sm + row_local * IN_DIM;
            const float* wp = W_sm + 2 * lane;
            #pragma unroll 8
            for (int c = 0; c < IN_DIM; c += 4) {
                float4 xv = *(const float4*)&xr[c];
                float2 p0 = *(const float2*)&wp[(c + 0) * KA_WPITCH];
                float2 p1 = *(const float2*)&wp[(c + 1) * KA_WPITCH];
                float2 p2 = *(const float2*)&wp[(c + 2) * KA_WPITCH];
                float2 p3 = *(const float2*)&wp[(c + 3) * KA_WPITCH];
                a0 += xv.x * p0.x; a1 += xv.x * p0.y;
                a0 += xv.y * p1.x; a1 += xv.y * p1.y;
                a0 += xv.z * p2.x; a1 += xv.z * p2.y;
                a0 += xv.w * p3.x; a1 += xv.w * p3.y;
            }
        }
        const int row = row0 + row_local;
        const float m = mask[row];
        const int k0 = 2 * lane;
        float v0 = (rs * (a0 - mu * sW_sm[k0    ]) + b[k0    ]) * m;
        float v1 = (rs * (a1 - mu * sW_sm[k0 + 1]) + b[k0 + 1]) * m;
        const int s = row >> 9, ip = row & 511;
        if (lane < 16) {
            *(float2*)&g_Lbuf[((size_t)ip * S_DIM + s) * PROJ + k0] = make_float2(v0, v1);
        } else {
            *(float2*)&g_Rbuf[((size_t)s * L_DIM + ip) * PROJ + (k0 - 32)] = make_float2(v0, v1);
        }
    }
}

// ---------------------------------------------------------------------------
// Kernel B (occ 2): per (i, 16-wide j-tile)
//  stage 1: G[j][d][e] = sum_s l[s,i,d]*r[s,j,e]   (r ring-3, 1 sync/chunk)
//  stage 2: out[j,f] = sum_de G * W, W streamed per-d (ring-2, 2 sync/d)
// smem floats:
//   [0,4096)       l_sm            (stage2: W buf 0; epilogue: pbuf lo)
//   [4096,10240)   rc ring-3 x2048 (stage2: W buf 1 in [4096,8192); pbuf hi)
//   [10240,26624)  G [j][d][e]     (pre-stage1: mjs alias)
//   [26624,26640)  normr
//   [26640,26768)  mi
// ---------------------------------------------------------------------------
#define KB_G_OFF   10240
#define KB_NR_OFF  26624
#define KB_MI_OFF  26640
#define KB_SMEM_FLOATS 26768

__global__ void __launch_bounds__(256, 2) Node2Edge_kB(
    const float* __restrict__ Wout, const float* __restrict__ bias,
    const float* __restrict__ mask, float* __restrict__ out)
{
    extern __shared__ float smb[];
    float* l_sm  = smb;
    float* rc    = smb + 4096;
    float* G_sm  = smb + KB_G_OFF;
    float* normr = smb + KB_NR_OFF;
    float* mi    = smb + KB_MI_OFF;
    float* mjs   = G_sm;            // alias before stage 1 writes G

    const int t  = threadIdx.x;
    const int i  = blockIdx.y;
    const int j0 = blockIdx.x * JT;

    // r chunk loader: chunk ch = 4 s rows; rbuf[s][j][e]; ring-3
    auto issue_r = [&](int ch, int buf) {
        unsigned dst0 = (unsigned)__cvta_generic_to_shared(rc + buf * 2048);
        #pragma unroll
        for (int q = 0; q < 2; q++) {
            int v = t + 256 * q;             // 512 float4
            int e4 = v & 7, j = (v >> 3) & 15, s = v >> 7;
            unsigned dst = dst0 + (unsigned)(((s * JT + j) * 32 + e4 * 4) * 4);
            const float* src = g_Rbuf + ((size_t)(ch * 4 + s) * L_DIM + j0 + j) * PROJ + e4 * 4;
            cp16(dst, src);
        }
        cpcommit();
    };
    issue_r(0, 0);
    issue_r(1, 1);

    // l for row i
    {
        const float4* Ls = (const float4*)(g_Lbuf + (size_t)i * S_DIM * PROJ);
        float4* Ld = (float4*)l_sm;
        #pragma unroll
        for (int q = 0; q < 4; q++) Ld[t + 256 * q] = Ls[t + 256 * q];
    }
    // masks
    if (t < 128) mi[t] = mask[t * L_DIM + i];
    #pragma unroll
    for (int q = 0; q < 8; q++) {
        int v = t + 256 * q;                 // 2048 = 128 s x 16 j
        int s = v >> 4, jm = v & 15;
        mjs[v] = mask[s * L_DIM + j0 + jm];
    }
    __syncthreads();
    if (t < JT) {
        float acc = 0.f;
        #pragma unroll 8
        for (int s = 0; s < S_DIM; s++) acc += mi[s] * mjs[s * JT + t];
        normr[t] = 1.0f / (acc + 0.001f);
    }

    // ===== stage 1 ===== (ring-3: one sync per chunk)
    const int e  = t & 31;
    const int jq = t >> 5;                   // warp -> j pair {2jq, 2jq+1}
    ull acc[2][16];
    #pragma unroll
    for (int a = 0; a < 2; a++)
        #pragma unroll
        for (int d2 = 0; d2 < 16; d2++) acc[a][d2] = 0ULL;

    #pragma unroll 1
    for (int ch = 0; ch < 32; ch++) {
        // sync: all warps finished compute(ch-1) -> buf[(ch+2)%3] (== (ch-1)%3) is free;
        // first iter doubles as the mjs/normr barrier.
        __syncthreads();
        if (ch + 2 < 32) { issue_r(ch + 2, (ch + 2) % 3); cpwait2(); }
        else if (ch + 1 < 32) { cpwait1(); }
        else { cpwait0(); }
        const float* rbuf = rc + (ch % 3) * 2048;
        #pragma unroll
        for (int s = 0; s < 4; s++) {
            ull lv[16];
            const ulonglong2* lrow = (const ulonglong2*)(l_sm + (ch * 4 + s) * 32);
            #pragma unroll
            for (int q = 0; q < 8; q++) { ulonglong2 u = lrow[q]; lv[2*q] = u.x; lv[2*q+1] = u.y; }
            #pragma unroll
            for (int jj = 0; jj < 2; jj++) {
                float rv = rbuf[(s * JT + jq * 2 + jj) * 32 + e];
                ull rr = pack2(rv, rv);
                #pragma unroll
                for (int d2 = 0; d2 < 16; d2++) fma2(acc[jj][d2], lv[d2], rr);
            }
        }
    }
    __syncthreads();   // all reads of l_sm / rc done before W streams overwrite

    // W streamer: per d, 4096 floats into [buf*4096, buf*4096+4096)
    auto issue_w = [&](int d, int buf) {
        unsigned dst0 = (unsigned)__cvta_generic_to_shared(smb + buf * 4096);
        const float* src0 = Wout + (size_t)d * 4096;
        #pragma unroll
        for (int q = 0; q < 4; q++) {
            int v = t + 256 * q;             // 1024 float4
            cp16(dst0 + (unsigned)(v * 16), src0 + v * 4);
        }
        cpcommit();
    };
    issue_w(0, 0);

    // write G[j][d][e]
    #pragma unroll
    for (int jj = 0; jj < 2; jj++) {
        const int j = jq * 2 + jj;
        #pragma unroll
        for (int d2 = 0; d2 < 16; d2++) {
            float g0, g1; unpack2(acc[jj][d2], g0, g1);
            G_sm[(j * 32 + 2 * d2    ) * 32 + e] = g0;
            G_sm[(j * 32 + 2 * d2 + 1) * 32 + e] = g1;
        }
    }
    __syncthreads();

    // ===== stage 2 =====
    const int fq = t & 31;                   // f = 4*fq
    const int w  = t >> 5;
    const int eh = w & 3;                    // e block [eh*8, eh*8+8)
    const int jh = w >> 2;                   // j block [jh*8, jh*8+8)
    ull a2[8][2];
    #pragma unroll
    for (int j8 = 0; j8 < 8; j8++) { a2[j8][0] = 0ULL; a2[j8][1] = 0ULL; }

    #pragma unroll 1
    for (int d = 0; d < 32; d++) {
        if (d + 1 < 32) { issue_w(d + 1, (d + 1) & 1); cpwait1(); }
        else            { cpwait0(); }
        __syncthreads();
        const float* wb = smb + (d & 1) * 4096;
        #pragma unroll
        for (int eq = 0; eq < 2; eq++) {
            const int e0 = eh * 8 + eq * 4;
            float4 gv[8];
            #pragma unroll
            for (int j8 = 0; j8 < 8; j8++)
                gv[j8] = *(const float4*)&G_sm[((jh * 8 + j8) * 32 + d) * 32 + e0];
            #pragma unroll
            for (int ee = 0; ee < 4; ee++) {
                float4 wv = *(const float4*)&wb[(e0 + ee) * OUT_F + 4 * fq];
                ull w01 = pack2(wv.x, wv.y);
                ull w23 = pack2(wv.z, wv.w);
                #pragma unroll
                for (int j8 = 0; j8 < 8; j8++) {
                    float g = (ee == 0) ? gv[j8].x : (ee == 1) ? gv[j8].y
                            : (ee == 2) ? gv[j8].z : gv[j8].w;
                    ull gg = pack2(g, g);
                    fma2(a2[j8][0], w01, gg);
                    fma2(a2[j8][1], w23, gg);
                }
            }
        }
        __syncthreads();
    }

    // partials -> smem [0, 8192): pbuf[(eh*16 + j)*128 + 4*fq]
    float* pbuf = smb;
    #pragma unroll
    for (int j8 = 0; j8 < 8; j8++) {
        float v0, v1, v2, v3;
        unpack2(a2[j8][0], v0, v1);
        unpack2(a2[j8][1], v2, v3);
        *(float4*)&pbuf[((eh * JT + jh * 8 + j8) * OUT_F) + 4 * fq] = make_float4(v0, v1, v2, v3);
    }
    __syncthreads();

    // reduce 4 eh groups + epilogue. Tile = 16j x 128f = 512 float4 -> 2/thread.
    #pragma unroll
    for (int q = 0; q < 2; q++) {
        int idx4 = t + 256 * q;
        int j = idx4 >> 5;
        const float4* p = (const float4*)pbuf;
        float4 s0 = p[idx4];
        float4 s1 = p[idx4 + 512];
        float4 s2 = p[idx4 + 1024];
        float4 s3 = p[idx4 + 1536];
        float4 bb = ((const float4*)bias)[idx4 & 31];
        float nr = normr[j];
        float4 o;
        o.x = (s0.x + s1.x + s2.x + s3.x + bb.x) * nr;
        o.y = (s0.y + s1.y + s2.y + s3.y + bb.y) * nr;
        o.z = (s0.z + s1.z + s2.z + s3.z + bb.z) * nr;
        o.w = (s0.w + s1.w + s2.w + s3.w + bb.w) * nr;
        ((float4*)(out + (size_t)i * (L_DIM * OUT_F) + (size_t)j0 * OUT_F))[idx4] = o;
    }
}

// ---------------------------------------------------------------------------
extern "C" void kernel_launch(void* const* d_in, const int* in_sizes, int n_in,
                              void* d_out, int out_size)
{
    const float* node_repr = (const float*)d_in[0];
    const float* mask      = (const float*)d_in[1];
    const float* w_proj    = (const float*)d_in[2];
    const float* b_proj    = (const float*)d_in[3];
    const float* out_w     = (const float*)d_in[4];
    const float* out_bias  = (const float*)d_in[5];
    float* out = (float*)d_out;

    const int smemA = KA_SMEM_FLOATS * 4;
    const int smemB = KB_SMEM_FLOATS * 4;
    cudaFuncSetAttribute(Node2Edge_kA, cudaFuncAttributeMaxDynamicSharedMemorySize, smemA);
    cudaFuncSetAttribute(Node2Edge_kB, cudaFuncAttributeMaxDynamicSharedMemorySize, smemB);

    Node2Edge_kA<<<(S_DIM * L_DIM) / 32, 256, smemA>>>(node_repr, mask, w_proj, b_proj);
    Node2Edge_kB<<<dim3(L_DIM / JT, L_DIM), 256, smemB>>>(out_w, out_bias, mask, out);
}

// round 14
// speedup vs baseline: 2.2329x; 2.2329x over previous
#include <cuda_runtime.h>
#include <cuda_bf16.h>
#include <cstdint>
#include <cstddef>

#define L_DIM 512
#define S_DIM 128
#define IN_DIM 256
#define OUT_F 128
using u32 = unsigned int;
using uch = unsigned char;
using us  = unsigned short;

__device__ __forceinline__ u32 smem_u32(const void* p){
    u32 a; asm("{ .reg .u64 t; cvta.to.shared.u64 t,%1; cvt.u32.u64 %0,t;}":"=r"(a):"l"(p)); return a;
}
__device__ __forceinline__ void cp16(u32 d, const void* s){
    asm volatile("cp.async.cg.shared.global [%0],[%1],16;"::"r"(d),"l"(s));
}
#define CPC()  asm volatile("cp.async.commit_group;":::"memory")
#define CPW0() asm volatile("cp.async.wait_group 0;":::"memory")
#define CPW1() asm volatile("cp.async.wait_group 1;":::"memory")
#define LDSM4(R,a) asm volatile("ldmatrix.sync.aligned.m8n8.x4.shared.b16 {%0,%1,%2,%3},[%4];" \
    :"=r"((R)[0]),"=r"((R)[1]),"=r"((R)[2]),"=r"((R)[3]):"r"(a))
#define MMA(C,A,b0,b1) asm volatile( \
    "mma.sync.aligned.m16n8k16.row.col.f32.bf16.bf16.f32 {%0,%1,%2,%3},{%4,%5,%6,%7},{%8,%9},{%0,%1,%2,%3};" \
    :"+f"((C)[0]),"+f"((C)[1]),"+f"((C)[2]),"+f"((C)[3]) \
    :"r"((A)[0]),"r"((A)[1]),"r"((A)[2]),"r"((A)[3]),"r"(b0),"r"(b1))

__device__ __forceinline__ void bsplit(float v, us& h, us& l){
    __nv_bfloat16 hb = __float2bfloat16(v);
    __nv_bfloat16 lb = __float2bfloat16(v - __bfloat162float(hb));
    h = __bfloat16_as_ushort(hb); l = __bfloat16_as_ushort(lb);
}
__device__ __forceinline__ void packHL(float a, float b, u32& H, u32& L){
    us h0,l0,h1,l1; bsplit(a,h0,l0); bsplit(b,h1,l1);
    H = (u32)h0 | ((u32)h1<<16); L = (u32)l0 | ((u32)l1<<16);
}

// Operand images, plain row-major bf16, k-contiguous rows.
__device__ uch g_Rh[16384*256];  // row = jt*128 + (jj*32+e), 128 s * 2B
__device__ uch g_Rl[16384*256];
__device__ uch g_Lh[16384*256];  // row = i*32 + d
__device__ uch g_Ll[16384*256];
__device__ uch g_Wh[128*2048];   // row = f, k = e*32+d (1024 * 2B)
__device__ uch g_Wl[128*2048];
__device__ uch g_Gh[536870912];  // row = i*512+j, k = e*32+d (1024*2B rows)
__device__ uch g_Gl[536870912];

// ================= kA: LN + proj + mask -> bf16 hi/lo images =================
#define KA_WPITCH 66
#define KA_SMEM_FLOATS (IN_DIM*KA_WPITCH + 32*IN_DIM + 64)
__global__ void __launch_bounds__(256) kA(
    const float* __restrict__ x, const float* __restrict__ mask,
    const float* __restrict__ W, const float* __restrict__ b)
{
    extern __shared__ float sma[];
    float* W_sm = sma;
    float* x_sm = sma + IN_DIM*KA_WPITCH;
    float* sW_sm = x_sm + 32*IN_DIM;
    const int t = threadIdx.x;
    {
        const float4* Wg = (const float4*)W;
        #pragma unroll
        for (int q = 0; q < 16; q++){
            int i4 = t + 256*q; float4 v = Wg[i4];
            int lin = i4*4, k = lin>>8, c = lin&255;
            W_sm[(c+0)*KA_WPITCH+k]=v.x; W_sm[(c+1)*KA_WPITCH+k]=v.y;
            W_sm[(c+2)*KA_WPITCH+k]=v.z; W_sm[(c+3)*KA_WPITCH+k]=v.w;
        }
    }
    const int row0 = blockIdx.x*32;
    {
        const float4* xs = (const float4*)(x + (size_t)row0*IN_DIM);
        float4* xd = (float4*)x_sm;
        #pragma unroll
        for (int q = 0; q < 8; q++) xd[t+256*q] = xs[t+256*q];
    }
    __syncthreads();
    if (t < 64){
        float s = 0.f;
        #pragma unroll 8
        for (int c = 0; c < IN_DIM; c++) s += W_sm[c*KA_WPITCH+t];
        sW_sm[t] = s;
    }
    __syncthreads();
    const int w = t>>5, lane = t&31;
    #pragma unroll 1
    for (int rr = 0; rr < 4; rr++){
        const int rl = w*4+rr;
        float s1 = 0.f, s2 = 0.f;
        #pragma unroll
        for (int q = 0; q < 8; q++){ float v = x_sm[rl*IN_DIM+lane+32*q]; s1 += v; s2 += v*v; }
        #pragma unroll
        for (int off = 16; off; off >>= 1){
            s1 += __shfl_xor_sync(0xffffffffu, s1, off);
            s2 += __shfl_xor_sync(0xffffffffu, s2, off);
        }
        const float mu = s1*(1.f/256.f);
        const float rs = rsqrtf(s2*(1.f/256.f) - mu*mu + 1e-5f);
        float a0 = 0.f, a1 = 0.f;
        {
            const float* xr = x_sm + rl*IN_DIM;
            const float* wp = W_sm + 2*lane;
            #pragma unroll 8
            for (int c = 0; c < IN_DIM; c += 4){
                float4 xv = *(const float4*)&xr[c];
                float2 p0 = *(const float2*)&wp[(c+0)*KA_WPITCH];
                float2 p1 = *(const float2*)&wp[(c+1)*KA_WPITCH];
                float2 p2 = *(const float2*)&wp[(c+2)*KA_WPITCH];
                float2 p3 = *(const float2*)&wp[(c+3)*KA_WPITCH];
                a0 += xv.x*p0.x; a1 += xv.x*p0.y; a0 += xv.y*p1.x; a1 += xv.y*p1.y;
                a0 += xv.z*p2.x; a1 += xv.z*p2.y; a0 += xv.w*p3.x; a1 += xv.w*p3.y;
            }
        }
        const int row = row0+rl;
        const float m = mask[row];
        const int k0 = 2*lane;
        float v0 = (rs*(a0 - mu*sW_sm[k0  ]) + b[k0  ])*m;
        float v1 = (rs*(a1 - mu*sW_sm[k0+1]) + b[k0+1])*m;
        const int s = row>>9, ip = row&511;
        us h0,l0,h1,l1; bsplit(v0,h0,l0); bsplit(v1,h1,l1);
        if (lane < 16){   // l: rows d=k0,k0+1 of image i=ip
            size_t b0 = ((size_t)ip*32 + k0)*256 + s*2;
            *(us*)(g_Lh+b0)=h0; *(us*)(g_Ll+b0)=l0;
            *(us*)(g_Lh+b0+256)=h1; *(us*)(g_Ll+b0+256)=l1;
        } else {          // r: rows m=(ip&3)*32+e of image jt=ip>>2
            int m2 = (ip&3)*32 + (k0-32);
            size_t b0 = ((size_t)(ip>>2)*128 + m2)*256 + s*2;
            *(us*)(g_Rh+b0)=h0; *(us*)(g_Rl+b0)=l0;
            *(us*)(g_Rh+b0+256)=h1; *(us*)(g_Rl+b0+256)=l1;
        }
    }
}

// ================= kW: repack out_weights [d*32+e][f] -> Wt[f][e*32+d] ========
__global__ void __launch_bounds__(256) kW(const float* __restrict__ Wout){
    const int f = blockIdx.x, t = threadIdx.x;
    #pragma unroll
    for (int q = 0; q < 4; q++){
        int k = t + 256*q;           // 0..1023
        int d = k&31, e = k>>5;
        us h,l; bsplit(Wout[(size_t)(d*32+e)*OUT_F + f], h, l);
        *(us*)(g_Wh + (size_t)f*2048 + k*2) = h;
        *(us*)(g_Wl + (size_t)f*2048 + k*2) = l;
    }
}

// ================= kB1: G = r x l (M=128(4j,32e), N=32d, K=128s) ==============
// smem: Rh[0,32K) Rl[32K,64K) L dbuf 2x16K [64K..96K) (hi 8K + lo 8K each)
#define KB1_SMEM 98304
__global__ void __launch_bounds__(256,2) kB1(){
    extern __shared__ __align__(128) uch sm1[];
    const u32 sb = smem_u32(sm1);
    const int t = threadIdx.x, w = t>>5, lane = t&31;
    const int jt = blockIdx.x, i0 = blockIdx.y*64;

    {   // prologue: R (hi+lo) + L0 in one group
        #pragma unroll
        for (int q = 0; q < 8; q++){
            int v = t+256*q, row = v>>4, ch = v&15;
            u32 d = sb + row*256 + ((ch^(row&7))<<4);
            size_t s = ((size_t)jt*128 + row)*256 + ch*16;
            cp16(d, g_Rh+s); cp16(d+32768, g_Rl+s);
        }
        #pragma unroll
        for (int q = 0; q < 2; q++){
            int v = t+256*q, row = v>>4, ch = v&15;
            u32 d = sb + 65536 + row*256 + ((ch^(row&7))<<4);
            size_t s = ((size_t)i0*32 + row)*256 + ch*16;
            cp16(d, g_Lh+s); cp16(d+8192, g_Ll+s);
        }
        CPC();
    }
    const int m0 = w*16;
    const int aRow = m0 + (lane&15);
    const int bRow = ((lane>>4)<<3) + (lane&7);
    const int jg = jt*4 + (w>>1), eb = (w&1)*16;
    const int cr = lane>>2, cc = (lane&3)*2;

    #pragma unroll 1
    for (int ii = 0; ii < 64; ii++){
        __syncthreads();                       // prev compute done -> buf free
        if (ii+1 < 64){
            int nb = (ii+1)&1;
            #pragma unroll
            for (int q = 0; q < 2; q++){
                int v = t+256*q, row = v>>4, ch = v&15;
                u32 d = sb + 65536 + nb*16384 + row*256 + ((ch^(row&7))<<4);
                size_t s = ((size_t)(i0+ii+1)*32 + row)*256 + ch*16;
                cp16(d, g_Lh+s); cp16(d+8192, g_Ll+s);
            }
            CPC(); CPW1();
        } else CPW0();
        __syncthreads();                       // L(ii) visible to all

        const u32 Lb = sb + 65536 + (ii&1)*16384;
        float C[4][4] = {};
        #pragma unroll
        for (int ks = 0; ks < 8; ks++){
            u32 Ah[4], Al[4], B0h[4], B1h[4], B0l[4], B1l[4];
            u32 ach = (u32)aRow*256 + ((((ks*2 + (lane>>4)))^(aRow&7))<<4);
            LDSM4(Ah, sb + ach); LDSM4(Al, sb + 32768 + ach);
            int r0 = bRow, r1 = 16 + bRow;
            u32 kc = ks*2 + ((lane>>3)&1);
            u32 b0c = (u32)r0*256 + ((kc^(r0&7))<<4);
            u32 b1c = (u32)r1*256 + ((kc^(r1&7))<<4);
            LDSM4(B0h, Lb + b0c); LDSM4(B1h, Lb + b1c);
            LDSM4(B0l, Lb + 8192 + b0c); LDSM4(B1l, Lb + 8192 + b1c);
            MMA(C[0],Ah,B0h[0],B0h[1]); MMA(C[1],Ah,B0h[2],B0h[3]);
            MMA(C[2],Ah,B1h[0],B1h[1]); MMA(C[3],Ah,B1h[2],B1h[3]);
            MMA(C[0],Ah,B0l[0],B0l[1]); MMA(C[1],Ah,B0l[2],B0l[3]);
            MMA(C[2],Ah,B1l[0],B1l[1]); MMA(C[3],Ah,B1l[2],B1l[3]);
            MMA(C[0],Al,B0h[0],B0h[1]); MMA(C[1],Al,B0h[2],B0h[3]);
            MMA(C[2],Al,B1h[0],B1h[1]); MMA(C[3],Al,B1h[2],B1h[3]);
        }
        // store G hi/lo: row (i,j), k = e*32 + d
        const size_t rowb = ((size_t)(i0+ii)*512 + jg)*2048;
        #pragma unroll
        for (int nt = 0; nt < 4; nt++){
            u32 H, L;
            packHL(C[nt][0], C[nt][1], H, L);
            size_t o = rowb + (size_t)((eb+cr)*32 + cc + nt*8)*2;
            *(u32*)(g_Gh+o) = H; *(u32*)(g_Gl+o) = L;
            packHL(C[nt][2], C[nt][3], H, L);
            o = rowb + (size_t)((eb+cr+8)*32 + cc + nt*8)*2;
            *(u32*)(g_Gh+o) = H; *(u32*)(g_Gl+o) = L;
        }
    }
}

// ================= kB2: out = G x Wt (M=128j, N=128f, K=3x1024) ===============
// smem: A dbuf 2x16K [0,32K), B dbuf 2x16K [32K,64K), normr[128] @64K, mi[128]
#define KB2_SMEM (65536 + 1024)
__global__ void __launch_bounds__(256,2) kB2(
    const float* __restrict__ bias, const float* __restrict__ mask, float* __restrict__ out)
{
    extern __shared__ __align__(128) uch sm2[];
    const u32 sb = smem_u32(sm2);
    float* normr = (float*)(sm2 + 65536);
    float* mi    = (float*)(sm2 + 65536 + 512);
    const int t = threadIdx.x, w = t>>5, lane = t&31;
    const int jt2 = blockIdx.x, i = blockIdx.y;

    auto issue = [&](int step, int buf){
        int p = step>>4, c = step&15;
        const uch* As = (p==2) ? g_Gl : g_Gh;
        const uch* Bs = (p==1) ? g_Wl : g_Wh;
        size_t abase = ((size_t)i*512 + jt2*128)*2048 + c*128;
        size_t bbase = (size_t)c*128;
        #pragma unroll
        for (int q = 0; q < 4; q++){
            int v = t+256*q, row = v>>3, ch = v&7;
            u32 sw = ((ch^(row&7))<<4);
            cp16(sb + buf*16384 + row*128 + sw, As + abase + (size_t)row*2048 + ch*16);
            cp16(sb + 32768 + buf*16384 + row*128 + sw, Bs + bbase + (size_t)row*2048 + ch*16);
        }
        CPC();
    };
    issue(0, 0);
    if (t < 128) mi[t] = mask[t*L_DIM + i];
    __syncthreads();
    if (t < 128){
        float a = 0.f;
        #pragma unroll 8
        for (int s = 0; s < 128; s++) a += mi[s]*mask[s*L_DIM + jt2*128 + t];
        normr[t] = 1.0f/(a + 0.001f);
    }

    const int m0 = w*16;
    const int aRow = m0 + (lane&15);
    const int bRow = ((lane>>4)<<3) + (lane&7);
    float C[16][4] = {};

    #pragma unroll 1
    for (int s = 0; s < 48; s++){
        __syncthreads();
        if (s+1 < 48){ issue(s+1, (s+1)&1); CPW1(); } else CPW0();
        __syncthreads();
        const u32 Ab = sb + (s&1)*16384;
        const u32 Bb = sb + 32768 + (s&1)*16384;
        #pragma unroll
        for (int ks = 0; ks < 4; ks++){
            u32 A[4];
            u32 ach = (u32)aRow*128 + ((((ks*2 + (lane>>4)))^(aRow&7))<<4);
            LDSM4(A, Ab + ach);
            u32 kc = ks*2 + ((lane>>3)&1);
            #pragma unroll
            for (int bp = 0; bp < 8; bp++){
                u32 B[4];
                int r0 = bp*16 + bRow;
                LDSM4(B, Bb + (u32)r0*128 + ((kc^(r0&7))<<4));
                MMA(C[2*bp],   A, B[0], B[1]);
                MMA(C[2*bp+1], A, B[2], B[3]);
            }
        }
    }
    // epilogue
    const int cr = lane>>2, cc = (lane&3)*2;
    #pragma unroll
    for (int h = 0; h < 2; h++){
        int j = m0 + cr + h*8;
        float nr = normr[j];
        float* op = out + ((size_t)i*512 + jt2*128 + j)*OUT_F;
        #pragma unroll
        for (int nt = 0; nt < 16; nt++){
            int f = cc + nt*8;
            float2 o;
            o.x = (C[nt][2*h  ] + bias[f  ])*nr;
            o.y = (C[nt][2*h+1] + bias[f+1])*nr;
            *(float2*)(op + f) = o;
        }
    }
}

// ---------------------------------------------------------------------------
extern "C" void kernel_launch(void* const* d_in, const int* in_sizes, int n_in,
                              void* d_out, int out_size)
{
    const float* node_repr = (const float*)d_in[0];
    const float* mask      = (const float*)d_in[1];
    const float* w_proj    = (const float*)d_in[2];
    const float* b_proj    = (const float*)d_in[3];
    const float* out_w     = (const float*)d_in[4];
    const float* out_bias  = (const float*)d_in[5];
    float* out = (float*)d_out;

    const int smemA = KA_SMEM_FLOATS*4;
    cudaFuncSetAttribute(kA,  cudaFuncAttributeMaxDynamicSharedMemorySize, smemA);
    cudaFuncSetAttribute(kB1, cudaFuncAttributeMaxDynamicSharedMemorySize, KB1_SMEM);
    cudaFuncSetAttribute(kB2, cudaFuncAttributeMaxDynamicSharedMemorySize, KB2_SMEM);

    kA<<<(S_DIM*L_DIM)/32, 256, smemA>>>(node_repr, mask, w_proj, b_proj);
    kW<<<128, 256>>>(out_w);
    kB1<<<dim3(128, 8), 256, KB1_SMEM>>>();
    kB2<<<dim3(4, 512), 256, KB2_SMEM>>>(out_bias, mask, out);
}

// round 15
// speedup vs baseline: 2.2627x; 1.0134x over previous
#include <cuda_runtime.h>
#include <cuda_bf16.h>
#include <cstdint>
#include <cstddef>

#define L_DIM 512
#define S_DIM 128
#define IN_DIM 256
#define OUT_F 128
using u32 = unsigned int;
using uch = unsigned char;
using us  = unsigned short;

__device__ __forceinline__ u32 smem_u32(const void* p){
    u32 a; asm("{ .reg .u64 t; cvta.to.shared.u64 t,%1; cvt.u32.u64 %0,t;}":"=r"(a):"l"(p)); return a;
}
__device__ __forceinline__ void cp16(u32 d, const void* s){
    asm volatile("cp.async.cg.shared.global [%0],[%1],16;"::"r"(d),"l"(s));
}
#define CPC()  asm volatile("cp.async.commit_group;":::"memory")
#define CPW0() asm volatile("cp.async.wait_group 0;":::"memory")
#define CPW1() asm volatile("cp.async.wait_group 1;":::"memory")
#define LDSM4(R,a) asm volatile("ldmatrix.sync.aligned.m8n8.x4.shared.b16 {%0,%1,%2,%3},[%4];" \
    :"=r"((R)[0]),"=r"((R)[1]),"=r"((R)[2]),"=r"((R)[3]):"r"(a))
#define MMA(C,A,b0,b1) asm volatile( \
    "mma.sync.aligned.m16n8k16.row.col.f32.bf16.bf16.f32 {%0,%1,%2,%3},{%4,%5,%6,%7},{%8,%9},{%0,%1,%2,%3};" \
    :"+f"((C)[0]),"+f"((C)[1]),"+f"((C)[2]),"+f"((C)[3]) \
    :"r"((A)[0]),"r"((A)[1]),"r"((A)[2]),"r"((A)[3]),"r"(b0),"r"(b1))

__device__ __forceinline__ void bsplit(float v, us& h, us& l){
    __nv_bfloat16 hb = __float2bfloat16(v);
    __nv_bfloat16 lb = __float2bfloat16(v - __bfloat162float(hb));
    h = __bfloat16_as_ushort(hb); l = __bfloat16_as_ushort(lb);
}
__device__ __forceinline__ void packHL(float a, float b, u32& H, u32& L){
    us h0,l0,h1,l1; bsplit(a,h0,l0); bsplit(b,h1,l1);
    H = (u32)h0 | ((u32)h1<<16); L = (u32)l0 | ((u32)l1<<16);
}

// Operand images, plain row-major bf16, k-contiguous rows.
__device__ uch g_Rh[16384*256];  // row = jt*128 + (jj*32+e), 128 s * 2B
__device__ uch g_Rl[16384*256];
__device__ uch g_Lh[16384*256];  // row = i*32 + d
__device__ uch g_Ll[16384*256];
__device__ uch g_Wh[128*2048];   // row = f, k = e*32+d
__device__ uch g_Wl[128*2048];
__device__ uch g_Gh[536870912];  // row = i*512+j, k = e*32+d (2048B rows)
__device__ uch g_Gl[536870912];

// ================= kA: LN + proj + mask -> bf16 hi/lo images =================
#define KA_WPITCH 66
#define KA_SMEM_FLOATS (IN_DIM*KA_WPITCH + 32*IN_DIM + 64)
__global__ void __launch_bounds__(256) kA(
    const float* __restrict__ x, const float* __restrict__ mask,
    const float* __restrict__ W, const float* __restrict__ b)
{
    extern __shared__ float sma[];
    float* W_sm = sma;
    float* x_sm = sma + IN_DIM*KA_WPITCH;
    float* sW_sm = x_sm + 32*IN_DIM;
    const int t = threadIdx.x;
    {
        const float4* Wg = (const float4*)W;
        #pragma unroll
        for (int q = 0; q < 16; q++){
            int i4 = t + 256*q; float4 v = Wg[i4];
            int lin = i4*4, k = lin>>8, c = lin&255;
            W_sm[(c+0)*KA_WPITCH+k]=v.x; W_sm[(c+1)*KA_WPITCH+k]=v.y;
            W_sm[(c+2)*KA_WPITCH+k]=v.z; W_sm[(c+3)*KA_WPITCH+k]=v.w;
        }
    }
    const int row0 = blockIdx.x*32;
    {
        const float4* xs = (const float4*)(x + (size_t)row0*IN_DIM);
        float4* xd = (float4*)x_sm;
        #pragma unroll
        for (int q = 0; q < 8; q++) xd[t+256*q] = xs[t+256*q];
    }
    __syncthreads();
    if (t < 64){
        float s = 0.f;
        #pragma unroll 8
        for (int c = 0; c < IN_DIM; c++) s += W_sm[c*KA_WPITCH+t];
        sW_sm[t] = s;
    }
    __syncthreads();
    const int w = t>>5, lane = t&31;
    #pragma unroll 1
    for (int rr = 0; rr < 4; rr++){
        const int rl = w*4+rr;
        float s1 = 0.f, s2 = 0.f;
        #pragma unroll
        for (int q = 0; q < 8; q++){ float v = x_sm[rl*IN_DIM+lane+32*q]; s1 += v; s2 += v*v; }
        #pragma unroll
        for (int off = 16; off; off >>= 1){
            s1 += __shfl_xor_sync(0xffffffffu, s1, off);
            s2 += __shfl_xor_sync(0xffffffffu, s2, off);
        }
        const float mu = s1*(1.f/256.f);
        const float rs = rsqrtf(s2*(1.f/256.f) - mu*mu + 1e-5f);
        float a0 = 0.f, a1 = 0.f;
        {
            const float* xr = x_sm + rl*IN_DIM;
            const float* wp = W_sm + 2*lane;
            #pragma unroll 8
            for (int c = 0; c < IN_DIM; c += 4){
                float4 xv = *(const float4*)&xr[c];
                float2 p0 = *(const float2*)&wp[(c+0)*KA_WPITCH];
                float2 p1 = *(const float2*)&wp[(c+1)*KA_WPITCH];
                float2 p2 = *(const float2*)&wp[(c+2)*KA_WPITCH];
                float2 p3 = *(const float2*)&wp[(c+3)*KA_WPITCH];
                a0 += xv.x*p0.x; a1 += xv.x*p0.y; a0 += xv.y*p1.x; a1 += xv.y*p1.y;
                a0 += xv.z*p2.x; a1 += xv.z*p2.y; a0 += xv.w*p3.x; a1 += xv.w*p3.y;
            }
        }
        const int row = row0+rl;
        const float m = mask[row];
        const int k0 = 2*lane;
        float v0 = (rs*(a0 - mu*sW_sm[k0  ]) + b[k0  ])*m;
        float v1 = (rs*(a1 - mu*sW_sm[k0+1]) + b[k0+1])*m;
        const int s = row>>9, ip = row&511;
        us h0,l0,h1,l1; bsplit(v0,h0,l0); bsplit(v1,h1,l1);
        if (lane < 16){
            size_t b0 = ((size_t)ip*32 + k0)*256 + s*2;
            *(us*)(g_Lh+b0)=h0; *(us*)(g_Ll+b0)=l0;
            *(us*)(g_Lh+b0+256)=h1; *(us*)(g_Ll+b0+256)=l1;
        } else {
            int m2 = (ip&3)*32 + (k0-32);
            size_t b0 = ((size_t)(ip>>2)*128 + m2)*256 + s*2;
            *(us*)(g_Rh+b0)=h0; *(us*)(g_Rl+b0)=l0;
            *(us*)(g_Rh+b0+256)=h1; *(us*)(g_Rl+b0+256)=l1;
        }
    }
}

// ================= kW: out_weights [d*32+e][f] -> Wt[f][e*32+d] ===============
__global__ void __launch_bounds__(256) kW(const float* __restrict__ Wout){
    const int f = blockIdx.x, t = threadIdx.x;
    #pragma unroll
    for (int q = 0; q < 4; q++){
        int k = t + 256*q;
        int d = k&31, e = k>>5;
        us h,l; bsplit(Wout[(size_t)(d*32+e)*OUT_F + f], h, l);
        *(us*)(g_Wh + (size_t)f*2048 + k*2) = h;
        *(us*)(g_Wl + (size_t)f*2048 + k*2) = l;
    }
}

// ================= kB1: G = r x l (M=128(4j,32e), N=32d, K=128s) ==============
// smem: Rh[0,32K) Rl[32K,64K) L dbuf 2x16K [64K..96K) (hi 8K + lo 8K each).
// After compute(ii), Lbuf(ii&1) is recycled as a 16KB staging tile for
// coalesced G writeback (hi 8K = 4j x 2048B, lo 8K).
#define KB1_SMEM 98304
__global__ void __launch_bounds__(256,2) kB1(){
    extern __shared__ __align__(128) uch sm1[];
    const u32 sb = smem_u32(sm1);
    const int t = threadIdx.x, w = t>>5, lane = t&31;
    const int jt = blockIdx.x, i0 = blockIdx.y*64;

    auto issueL = [&](int ii, int buf){
        #pragma unroll
        for (int q = 0; q < 2; q++){
            int v = t+256*q, row = v>>4, ch = v&15;
            u32 d = sb + 65536 + buf*16384 + row*256 + ((ch^(row&7))<<4);
            size_t s = ((size_t)(i0+ii)*32 + row)*256 + ch*16;
            cp16(d, g_Lh+s); cp16(d+8192, g_Ll+s);
        }
        CPC();
    };
    {   // prologue: R (hi+lo) + L0 in one group
        #pragma unroll
        for (int q = 0; q < 8; q++){
            int v = t+256*q, row = v>>4, ch = v&15;
            u32 d = sb + row*256 + ((ch^(row&7))<<4);
            size_t s = ((size_t)jt*128 + row)*256 + ch*16;
            cp16(d, g_Rh+s); cp16(d+32768, g_Rl+s);
        }
        #pragma unroll
        for (int q = 0; q < 2; q++){
            int v = t+256*q, row = v>>4, ch = v&15;
            u32 d = sb + 65536 + row*256 + ((ch^(row&7))<<4);
            size_t s = ((size_t)i0*32 + row)*256 + ch*16;
            cp16(d, g_Lh+s); cp16(d+8192, g_Ll+s);
        }
        CPC();
    }
    const int m0 = w*16;
    const int aRow = m0 + (lane&15);
    const int bRow = ((lane>>4)<<3) + (lane&7);
    const int jl = w>>1, eb = (w&1)*16;
    const int cr = lane>>2, cc = (lane&3)*2;

    #pragma unroll 1
    for (int ii = 0; ii < 64; ii++){
        __syncthreads();                       // writeback(ii-1) done -> buf reusable
        if (ii+1 < 64){ issueL(ii+1, (ii+1)&1); CPW1(); } else CPW0();
        __syncthreads();                       // L(ii) visible

        const u32 Lb = sb + 65536 + (ii&1)*16384;
        float C[4][4] = {};
        #pragma unroll
        for (int ks = 0; ks < 8; ks++){
            u32 Ah[4], Al[4], B0h[4], B1h[4], B0l[4], B1l[4];
            u32 ach = (u32)aRow*256 + ((((ks*2 + (lane>>4)))^(aRow&7))<<4);
            LDSM4(Ah, sb + ach); LDSM4(Al, sb + 32768 + ach);
            int r0 = bRow, r1 = 16 + bRow;
            u32 kc = ks*2 + ((lane>>3)&1);
            u32 b0c = (u32)r0*256 + ((kc^(r0&7))<<4);
            u32 b1c = (u32)r1*256 + ((kc^(r1&7))<<4);
            LDSM4(B0h, Lb + b0c); LDSM4(B1h, Lb + b1c);
            LDSM4(B0l, Lb + 8192 + b0c); LDSM4(B1l, Lb + 8192 + b1c);
            MMA(C[0],Ah,B0h[0],B0h[1]); MMA(C[1],Ah,B0h[2],B0h[3]);
            MMA(C[2],Ah,B1h[0],B1h[1]); MMA(C[3],Ah,B1h[2],B1h[3]);
            MMA(C[0],Ah,B0l[0],B0l[1]); MMA(C[1],Ah,B0l[2],B0l[3]);
            MMA(C[2],Ah,B1l[0],B1l[1]); MMA(C[3],Ah,B1l[2],B1l[3]);
            MMA(C[0],Al,B0h[0],B0h[1]); MMA(C[1],Al,B0h[2],B0h[3]);
            MMA(C[2],Al,B1h[0],B1h[1]); MMA(C[3],Al,B1h[2],B1h[3]);
        }
        __syncthreads();                       // all warps done reading L(ii)
        // stage C into Lbuf(ii&1): hi [0,8K) = [jl][k]*2B, lo [8K,16K)
        #pragma unroll
        for (int nt = 0; nt < 4; nt++){
            u32 H, L;
            packHL(C[nt][0], C[nt][1], H, L);
            u32 o = Lb + (u32)jl*2048 + (u32)(((eb+cr)*32 + cc + nt*8)*2);
            *(u32*)(sm1 + (o - sb)) = H; *(u32*)(sm1 + (o - sb) + 8192) = L;
            packHL(C[nt][2], C[nt][3], H, L);
            o = Lb + (u32)jl*2048 + (u32)(((eb+cr+8)*32 + cc + nt*8)*2);
            *(u32*)(sm1 + (o - sb)) = H; *(u32*)(sm1 + (o - sb) + 8192) = L;
        }
        __syncthreads();
        // coalesced writeback: 1024 uint4 (hi 512 + lo 512)
        {
            const uch* st = sm1 + 65536 + (ii&1)*16384;
            #pragma unroll
            for (int q = 0; q < 2; q++){
                int idx = t + 256*q;           // 0..511 (hi)
                int jj = idx>>7, wi = (idx&127)*16;
                size_t rowb = (((size_t)(i0+ii)*512) + jt*4 + jj)*2048;
                *(uint4*)(g_Gh + rowb + wi) = *(const uint4*)(st + jj*2048 + wi);
                *(uint4*)(g_Gl + rowb + wi) = *(const uint4*)(st + 8192 + jj*2048 + wi);
            }
        }
    }
}

// ================= kB2: out = G x Wt, chunk-major fused 3-product =============
// 32 chunks of k=32. Per chunk buffer (32KB): Ah 8K | Al 8K | Bh 8K | Bl 8K.
// dbuf 2x32KB = 64KB; normr/mi @64K. Warp grid: 4 j-warps x 2 f-warps.
// Rows are 64B pitch (32 k), swizzle (ch ^ ((row>>1)&3))<<4.
#define KB2_SMEM (65536 + 1024)
__global__ void __launch_bounds__(256,2) kB2(
    const float* __restrict__ bias, const float* __restrict__ mask, float* __restrict__ out)
{
    extern __shared__ __align__(128) uch sm2[];
    const u32 sb = smem_u32(sm2);
    float* normr = (float*)(sm2 + 65536);
    float* mi    = (float*)(sm2 + 65536 + 512);
    const int t = threadIdx.x, w = t>>5, lane = t&31;
    const int jt2 = blockIdx.x, i = blockIdx.y;

    auto issue = [&](int c, int buf){
        size_t abase = ((size_t)i*512 + jt2*128)*2048 + c*64;
        size_t bbase = (size_t)c*64;
        #pragma unroll
        for (int q = 0; q < 2; q++){
            int v = t+256*q, row = v>>2, ch = v&3;   // 512 rows-chunks per tile
            u32 sw = (u32)(((u32)ch ^ ((row>>1)&3))<<4);
            u32 d = sb + buf*32768 + row*64 + sw;
            size_t ao = abase + (size_t)row*2048 + ch*16;
            size_t bo = bbase + (size_t)row*2048 + ch*16;
            cp16(d,         g_Gh + ao);
            cp16(d + 8192,  g_Gl + ao);
            cp16(d + 16384, g_Wh + bo);
            cp16(d + 24576, g_Wl + bo);
        }
        CPC();
    };
    issue(0, 0);
    if (t < 128) mi[t] = mask[t*L_DIM + i];
    __syncthreads();
    if (t < 128){
        float a = 0.f;
        #pragma unroll 8
        for (int s = 0; s < 128; s++) a += mi[s]*mask[s*L_DIM + jt2*128 + t];
        normr[t] = 1.0f/(a + 0.001f);
    }

    const int m0 = (w&3)*32;         // j block (32 rows)
    const int f0 = (w>>2)*64;        // f block (64 rows)
    const int aLane = lane&15, aK = lane>>4;
    const int bRow = ((lane>>4)<<3) + (lane&7), bK = (lane>>3)&1;
    float C[2][8][4];
    #pragma unroll
    for (int a1 = 0; a1 < 2; a1++)
        #pragma unroll
        for (int a2 = 0; a2 < 8; a2++)
            #pragma unroll
            for (int a3 = 0; a3 < 4; a3++) C[a1][a2][a3] = 0.f;

    #pragma unroll 1
    for (int s = 0; s < 32; s++){
        __syncthreads();                         // compute(s-1) done -> buf free
        if (s+1 < 32){ issue(s+1, (s+1)&1); CPW1(); } else CPW0();
        __syncthreads();                         // chunk s visible
        const u32 Ab = sb + (s&1)*32768;
        const u32 Bb = Ab + 16384;
        #pragma unroll
        for (int ks = 0; ks < 2; ks++){
            u32 Ah[2][4], Al[2][4];
            #pragma unroll
            for (int mh = 0; mh < 2; mh++){
                int r = m0 + mh*16 + aLane;
                u32 kc = ks*2 + aK;
                u32 ac = (u32)r*64 + ((kc ^ ((r>>1)&3))<<4);
                LDSM4(Ah[mh], Ab + ac);
                LDSM4(Al[mh], Ab + 8192 + ac);
            }
            #pragma unroll
            for (int bp = 0; bp < 4; bp++){
                u32 Bh[4], Bl[4];
                int r0 = f0 + bp*16 + bRow;
                u32 kc = ks*2 + bK;
                u32 bc = (u32)r0*64 + ((kc ^ ((r0>>1)&3))<<4);
                LDSM4(Bh, Bb + bc);
                LDSM4(Bl, Bb + 8192 + bc);
                #pragma unroll
                for (int mh = 0; mh < 2; mh++){
                    MMA(C[mh][2*bp],   Ah[mh], Bh[0], Bh[1]);
                    MMA(C[mh][2*bp+1], Ah[mh], Bh[2], Bh[3]);
                    MMA(C[mh][2*bp],   Ah[mh], Bl[0], Bl[1]);
                    MMA(C[mh][2*bp+1], Ah[mh], Bl[2], Bl[3]);
                    MMA(C[mh][2*bp],   Al[mh], Bh[0], Bh[1]);
                    MMA(C[mh][2*bp+1], Al[mh], Bh[2], Bh[3]);
                }
            }
        }
    }
    // epilogue
    const int cr = lane>>2, cc = (lane&3)*2;
    #pragma unroll
    for (int mh = 0; mh < 2; mh++){
        #pragma unroll
        for (int h = 0; h < 2; h++){
            int j = m0 + mh*16 + cr + h*8;
            float nr = normr[j];
            float* op = out + ((size_t)i*512 + jt2*128 + j)*OUT_F;
            #pragma unroll
            for (int nt = 0; nt < 8; nt++){
                int f = f0 + (nt>>1)*16 + (nt&1)*8 + cc;
                float2 o;
                o.x = (C[mh][nt][2*h  ] + bias[f  ])*nr;
                o.y = (C[mh][nt][2*h+1] + bias[f+1])*nr;
                *(float2*)(op + f) = o;
            }
        }
    }
}

// ---------------------------------------------------------------------------
extern "C" void kernel_launch(void* const* d_in, const int* in_sizes, int n_in,
                              void* d_out, int out_size)
{
    const float* node_repr = (const float*)d_in[0];
    const float* mask      = (const float*)d_in[1];
    const float* w_proj    = (const float*)d_in[2];
    const float* b_proj    = (const float*)d_in[3];
    const float* out_w     = (const float*)d_in[4];
    const float* out_bias  = (const float*)d_in[5];
    float* out = (float*)d_out;

    const int smemA = KA_SMEM_FLOATS*4;
    cudaFuncSetAttribute(kA,  cudaFuncAttributeMaxDynamicSharedMemorySize, smemA);
    cudaFuncSetAttribute(kB1, cudaFuncAttributeMaxDynamicSharedMemorySize, KB1_SMEM);
    cudaFuncSetAttribute(kB2, cudaFuncAttributeMaxDynamicSharedMemorySize, KB2_SMEM);

    kA<<<(S_DIM*L_DIM)/32, 256, smemA>>>(node_repr, mask, w_proj, b_proj);
    kW<<<128, 256>>>(out_w);
    kB1<<<dim3(128, 8), 256, KB1_SMEM>>>();
    kB2<<<dim3(4, 512), 256, KB2_SMEM>>>(out_bias, mask, out);
}